// round 8
// baseline (speedup 1.0000x reference)
#include <cuda_runtime.h>
#include <cuda_bf16.h>
#include <math.h>
#include <stdint.h>

// ---------------------------------------------------------------------------
// Problem dims
// ---------------------------------------------------------------------------
#define BATCH 16
#define TQ 2048
#define TV 2048
#define DIM 1024
#define UNITS 1024

// ---------------------------------------------------------------------------
// tcgen05 guard for the plain compute_103 PTX pass
// ---------------------------------------------------------------------------
#if defined(__CUDA_ARCH_FEAT_SM103_ALL) || defined(__CUDA_ARCH_FEAT_SM100_ALL) || defined(__CUDA_ARCH_FEAT_SM101_ALL)
#define TCOK 1
#else
#define TCOK 0
#endif

// ---------------------------------------------------------------------------
// Scratch: [hi | lo] storage, row stride 2*K
// ---------------------------------------------------------------------------
__device__ __nv_bfloat16 g_qcat[(size_t)BATCH * TQ * 2 * UNITS];  // query  [hi|lo]
__device__ __nv_bfloat16 g_vcat[(size_t)BATCH * TV * 2 * DIM];    // values [hi|lo]
__device__ __nv_bfloat16 g_wtcat[(size_t)UNITS * 2 * DIM];        // W^T    [hi|lo]
__device__ __nv_bfloat16 g_kcat[(size_t)BATCH * TV * 2 * UNITS];  // keys   [hi|lo]
__device__ __nv_bfloat16 g_vtcat[(size_t)BATCH * DIM * 2 * TV];   // V^T    [hi|lo]
__device__ __nv_bfloat16 g_acat[(size_t)BATCH * TQ * 2 * TV];     // align  [hi|lo]

// ---------------------------------------------------------------------------
// PTX helpers
// ---------------------------------------------------------------------------
__device__ __forceinline__ uint32_t smem_u32(const void* p) {
    uint32_t a;
    asm("{ .reg .u64 t; cvta.to.shared.u64 t, %1; cvt.u32.u64 %0, t; }" : "=r"(a) : "l"(p));
    return a;
}
__device__ __forceinline__ uint32_t elect_one_pred() {
    uint32_t pred;
    asm volatile("{\n\t.reg .pred p;\n\telect.sync _|p, 0xFFFFFFFF;\n\tselp.b32 %0, 1, 0, p;\n\t}" : "=r"(pred));
    return pred;
}
__device__ __forceinline__ uint32_t cluster_rank() {
    uint32_t r;
    asm("mov.u32 %0, %%cluster_ctarank;" : "=r"(r));
    return r;
}
#define MBARRIER_INIT(addr, cnt) \
    asm volatile("mbarrier.init.shared.b64 [%0], %1;" :: "r"(addr), "r"((uint32_t)(cnt)) : "memory")
#define MBARRIER_ARRIVE_RANK(addr, rnk) \
    asm volatile("{\n\t.reg .b32 ra;\n\tmapa.shared::cluster.u32 ra, %0, %1;\n\t" \
                 "mbarrier.arrive.shared::cluster.b64 _, [ra];\n\t}" \
                 :: "r"(addr), "r"((uint32_t)(rnk)) : "memory")
#define MBARRIER_WAIT_PARITY(addr, parity) do { \
    uint32_t _m = (addr); uint32_t _p = (uint32_t)(parity); uint32_t _d; \
    asm volatile("{\n\t.reg .pred p;\n\tmbarrier.try_wait.parity.acquire.cta.shared::cta.b64 p, [%1], %2;\n\tselp.b32 %0, 1, 0, p;\n\t}" \
        : "=r"(_d) : "r"(_m), "r"(_p) : "memory"); \
    if (!_d) { \
        asm volatile("{\n\t.reg .pred P1;\n\tWL_%=:\n\tmbarrier.try_wait.parity.acquire.cta.shared::cta.b64 P1, [%0], %1, 0x989680;\n\t@P1 bra.uni WD_%=;\n\tbra.uni WL_%=;\n\tWD_%=:\n\t}" \
            :: "r"(_m), "r"(_p) : "memory"); \
    } } while (0)
#define CLUSTER_SYNC() do { \
    asm volatile("barrier.cluster.arrive.aligned;" ::: "memory"); \
    asm volatile("barrier.cluster.wait.aligned;" ::: "memory"); } while (0)

#if TCOK
#define TCGEN05_ALLOC_CG2(sp, n) \
    asm volatile("tcgen05.alloc.cta_group::2.sync.aligned.shared::cta.b32 [%0], %1;" :: "r"(sp), "r"((uint32_t)(n)) : "memory")
#define TCGEN05_DEALLOC_CG2(t, n) \
    asm volatile("tcgen05.dealloc.cta_group::2.sync.aligned.b32 %0, %1;" :: "r"(t), "r"((uint32_t)(n)))
#define TCGEN05_RELINQ_CG2() \
    asm volatile("tcgen05.relinquish_alloc_permit.cta_group::2.sync.aligned;")
#define TCGEN05_COMMIT_MC2(mb, mask) \
    asm volatile("tcgen05.commit.cta_group::2.mbarrier::arrive::one.shared::cluster.multicast::cluster.b64 [%0], %1;" \
                 :: "r"(mb), "h"((uint16_t)(mask)) : "memory")
#define TCGEN05_FENCE_AFTER() asm volatile("tcgen05.fence::after_thread_sync;" ::: "memory")
#define TCGEN05_WAIT_LD()     asm volatile("tcgen05.wait::ld.sync.aligned;" ::: "memory")
#define TCGEN05_LD_32X32B_X32(r, ta) \
    asm volatile("tcgen05.ld.sync.aligned.32x32b.x32.b32 " \
        "{%0, %1, %2, %3, %4, %5, %6, %7, %8, %9, %10, %11, %12, %13, %14, %15, " \
        " %16, %17, %18, %19, %20, %21, %22, %23, %24, %25, %26, %27, %28, %29, %30, %31}, [%32];" \
        : "=r"((r)[0]), "=r"((r)[1]), "=r"((r)[2]), "=r"((r)[3]), "=r"((r)[4]), "=r"((r)[5]), "=r"((r)[6]), "=r"((r)[7]), \
          "=r"((r)[8]), "=r"((r)[9]), "=r"((r)[10]), "=r"((r)[11]), "=r"((r)[12]), "=r"((r)[13]), "=r"((r)[14]), "=r"((r)[15]), \
          "=r"((r)[16]), "=r"((r)[17]), "=r"((r)[18]), "=r"((r)[19]), "=r"((r)[20]), "=r"((r)[21]), "=r"((r)[22]), "=r"((r)[23]), \
          "=r"((r)[24]), "=r"((r)[25]), "=r"((r)[26]), "=r"((r)[27]), "=r"((r)[28]), "=r"((r)[29]), "=r"((r)[30]), "=r"((r)[31]) \
        : "r"(ta))
#else
#define TCGEN05_ALLOC_CG2(sp, n)   ((void)0)
#define TCGEN05_DEALLOC_CG2(t, n)  ((void)0)
#define TCGEN05_RELINQ_CG2()       ((void)0)
#define TCGEN05_COMMIT_MC2(mb, m)  ((void)0)
#define TCGEN05_FENCE_AFTER()      ((void)0)
#define TCGEN05_WAIT_LD()          ((void)0)
#define TCGEN05_LD_32X32B_X32(r, ta) do { \
    _Pragma("unroll") for (int _i = 0; _i < 32; _i++) (r)[_i] = 0u; (void)(ta); } while (0)
#endif

#define CP_ASYNC16(dst, src) \
    asm volatile("cp.async.cg.shared.global [%0], [%1], 16;" :: "r"(dst), "l"(src) : "memory")
#define CP_COMMIT() asm volatile("cp.async.commit_group;" ::: "memory")
#define CP_WAIT(n)  asm volatile("cp.async.wait_group %0;" :: "n"(n) : "memory")
#define FENCE_ASYNC() asm volatile("fence.proxy.async;" ::: "memory")

#define SMEM_SWIZZLE_128B(off) ((off) ^ (((off) >> 3) & 0x70))

static __device__ __forceinline__ uint64_t make_desc(uint32_t addr) {
    const uint64_t base =
        (uint64_t(2) << 61) | (uint64_t(1) << 46) | (uint64_t(64) << 32) | (uint64_t(1) << 16);
    return base | ((uint64_t)(addr >> 4) & 0x3FFF);
}

// idesc kind::f16 bf16xbf16->f32, cg2: M=256 (16<<24), N=256 (32<<17)
#define GEMM_IDESC_CG2 0x10400490u

__device__ __forceinline__ void mma_f16_ss_cg2(uint32_t d, uint64_t ad, uint64_t bd, uint32_t en) {
#if TCOK
    asm volatile(
        "{\n\t.reg .pred p;\n\tsetp.ne.u32 p, %5, 0;\n\t"
        "tcgen05.mma.cta_group::2.kind::f16 [%0], %1, %2, %3, {%4,%4,%4,%4,%4,%4,%4,%4}, p;\n\t}"
        :: "r"(d), "l"(ad), "l"(bd), "r"(GEMM_IDESC_CG2), "r"(0u), "r"(en) : "memory");
#else
    (void)d; (void)ad; (void)bd; (void)en;
#endif
}

// ---------------------------------------------------------------------------
// split helpers
// ---------------------------------------------------------------------------
__device__ __forceinline__ void split1(float v, __nv_bfloat16& h, __nv_bfloat16& l) {
    h = __float2bfloat16(v);
    l = __float2bfloat16(v - __bfloat162float(h));
}
__device__ __forceinline__ uint2 pack4(__nv_bfloat16 a, __nv_bfloat16 b, __nv_bfloat16 c, __nv_bfloat16 d) {
    __nv_bfloat162 p0; p0.x = a; p0.y = b;
    __nv_bfloat162 p1; p1.x = c; p1.y = d;
    uint2 r;
    r.x = *reinterpret_cast<uint32_t*>(&p0);
    r.y = *reinterpret_cast<uint32_t*>(&p1);
    return r;
}

// fp32 [.., K] -> bf16 [hi K | lo K], row stride 2K
__global__ __launch_bounds__(256)
void split_rows(const float* __restrict__ src, __nv_bfloat16* __restrict__ dst,
                long long n, int K)
{
    long long e = ((long long)blockIdx.x * 256 + threadIdx.x) * 4;
    if (e >= n) return;
    float4 v = *(const float4*)(src + e);
    long long m = e / K;
    int k = (int)(e - m * K);
    __nv_bfloat16 h0, h1, h2, h3, l0, l1, l2, l3;
    split1(v.x, h0, l0); split1(v.y, h1, l1); split1(v.z, h2, l2); split1(v.w, h3, l3);
    long long base = m * (long long)(2 * K) + k;
    *(uint2*)(dst + base)     = pack4(h0, h1, h2, h3);
    *(uint2*)(dst + base + K) = pack4(l0, l1, l2, l3);
}

// transpose + split: src [R, C] fp32 -> dst [C, 2R] bf16 ([hi R | lo R])
__global__ __launch_bounds__(256)
void transpose_split(const float* __restrict__ src, __nv_bfloat16* __restrict__ dst,
                     int R, int C, long long sSrc, long long sDst)
{
    __shared__ float t[32][33];
    src += (long long)blockIdx.z * sSrc;
    dst += (long long)blockIdx.z * sDst;
    int r0 = blockIdx.x * 32;
    int c0 = blockIdx.y * 32;
    int tx = threadIdx.x, ty = threadIdx.y;  // block (32, 8)
    #pragma unroll
    for (int i = 0; i < 4; i++)
        t[ty + i * 8][tx] = src[(long long)(r0 + ty + i * 8) * C + (c0 + tx)];
    __syncthreads();
    #pragma unroll
    for (int i = 0; i < 4; i++) {
        int dr = c0 + ty + i * 8;
        int dc = r0 + tx;
        float v = t[tx][ty + i * 8];
        __nv_bfloat16 h, l; split1(v, h, l);
        __nv_bfloat16* p = dst + (long long)dr * (2 * R) + dc;
        p[0] = h;
        p[R] = l;
    }
}

// ---------------------------------------------------------------------------
// cg2 tcgen05 GEMM over logical segments (A: {hi,lo,hi}, B: {hi,hi,lo})
//   COMPILE-TIME cluster (2,1,1): pair = {blockIdx.x even, odd}.
//   Pair computes a 256x256 tile; each CTA loads its 128 A-rows (M half)
//   and 128 B-rows (N half). KBLK=64, 2-stage cp.async.
//   smem 66.5KB, TMEM 256 cols -> 2 CTAs/SM.
// mode 0: fp32 out Cf. mode 1: bias + split out Cs ([hi|lo], lo at +Nseg).
// ---------------------------------------------------------------------------
#define KBLK 64
#define ATILE 16384   // 128 rows x 128B
#define BTILE 16384   // 128 rows x 128B
#define GSMEM_BYTES (1024 + 2 * (ATILE + BTILE))

__global__ __launch_bounds__(128) __cluster_dims__(2, 1, 1)
void tcgemm2(const __nv_bfloat16* __restrict__ A, const __nv_bfloat16* __restrict__ B,
             float* __restrict__ Cf, __nv_bfloat16* __restrict__ Cs,
             const float* __restrict__ bias,
             int Kseg, int blkShift, int lda, int ldb, int ldc,
             long long sA, long long sB, long long sC,
             int Nseg, int mode)
{
    extern __shared__ char dsm[];
    uint32_t sbase = (smem_u32(dsm) + 1023) & ~1023u;
    const uint32_t tptr   = sbase;
    const uint32_t ready0 = sbase + 8;    // leader-side, count 2
    const uint32_t done0  = sbase + 24;   // per-CTA, count 1 (multicast commit)
    const uint32_t aoff0 = sbase + 1024;
    const uint32_t aoff1 = aoff0 + ATILE;
    const uint32_t boff0 = aoff1 + ATILE;
    const uint32_t boff1 = boff0 + BTILE;
    const uint32_t Aoff[2] = {aoff0, aoff1};
    const uint32_t Boff[2] = {boff0, boff1};

    const int tid = threadIdx.x;
    const int wid = tid >> 5;
    const int lane = tid & 31;
    const int z = blockIdx.z;
    const uint32_t rank = cluster_rank();

    if (wid == 0) TCGEN05_ALLOC_CG2(tptr, 256);
    if (tid == 0) {
        MBARRIER_INIT(ready0,     2);
        MBARRIER_INIT(ready0 + 8, 2);
        MBARRIER_INIT(done0,      1);
        MBARRIER_INIT(done0 + 8,  1);
    }
    __syncthreads();
    CLUSTER_SYNC();   // all mbarriers visible before any remote arrive / multicast
    uint32_t tmem;
    asm volatile("ld.shared.b32 %0, [%1];" : "=r"(tmem) : "r"(tptr));

    const __nv_bfloat16* Ab = A + (long long)z * sA;
    const __nv_bfloat16* Bb = B + (long long)z * sB;
    const int row0  = blockIdx.y * 256 + (int)rank * 128;       // this CTA's A rows / D rows
    const int col0  = (blockIdx.x >> 1) * 256;                   // tile N base
    const int brow0 = col0 + (int)rank * 128;                    // this CTA's B rows

    const int segA[3] = {0, Kseg, 0};
    const int segB[3] = {0, 0, Kseg};
    const int perSegM1 = (1 << blkShift) - 1;
    const int nkb = 3 << blkShift;

    auto colOf = [&](int kb, const int* seg) {
        return seg[kb >> blkShift] + (kb & perSegM1) * KBLK;
    };

    // 128 rows x 64 bf16 (128B/row), SW128 swizzle
    auto load_tile = [&](uint32_t smemTile, const __nv_bfloat16* g, int ld, int r0g, int cb) {
        #pragma unroll
        for (int s = 0; s < 8; s++) {
            int id = tid + s * 128;
            int r = id >> 3;
            int c = id & 7;
            const char* src = (const char*)(g + (long long)(r0g + r) * ld + cb) + c * 16;
            uint32_t dst = smemTile + SMEM_SWIZZLE_128B(r * 128 + c * 16);
            CP_ASYNC16(dst, src);
        }
    };

    int ph[2] = {0, 0};    // done-barrier phases (all threads)
    int rph[2] = {0, 0};   // ready-barrier phases (leader warp only)

    load_tile(Aoff[0], Ab, lda, row0, colOf(0, segA));
    load_tile(Boff[0], Bb, ldb, brow0, colOf(0, segB));
    CP_COMMIT();

    for (int kb = 0; kb < nkb; kb++) {
        const int buf = kb & 1, nb = buf ^ 1;
        if (kb + 1 < nkb) {
            if (kb >= 1) {  // buffer nb last consumed by MMA of block kb-1
                MBARRIER_WAIT_PARITY(done0 + 8 * nb, ph[nb] & 1);
                ph[nb]++;
            }
            load_tile(Aoff[nb], Ab, lda, row0, colOf(kb + 1, segA));
            load_tile(Boff[nb], Bb, ldb, brow0, colOf(kb + 1, segB));
            CP_COMMIT();
            CP_WAIT(1);
        } else {
            CP_WAIT(0);
        }
        FENCE_ASYNC();
        __syncthreads();
        if (tid == 0) MBARRIER_ARRIVE_RANK(ready0 + 8 * buf, 0);  // signal leader: my half ready
        if (rank == 0 && wid == 0) {
            MBARRIER_WAIT_PARITY(ready0 + 8 * buf, rph[buf] & 1);
            rph[buf]++;
            if (elect_one_pred()) {
                uint64_t ad = make_desc(Aoff[buf]);
                uint64_t bd = make_desc(Boff[buf]);
                #pragma unroll
                for (int s = 0; s < 4; s++)
                    mma_f16_ss_cg2(tmem, ad + s * 2, bd + s * 2, (kb > 0 || s > 0) ? 1u : 0u);
                TCGEN05_COMMIT_MC2(done0 + 8 * buf, 0x3);
            }
        }
    }

    const int lastbuf = (nkb - 1) & 1;
    MBARRIER_WAIT_PARITY(done0 + 8 * lastbuf, ph[lastbuf] & 1);
    TCGEN05_FENCE_AFTER();

    // each CTA reads its own 128 D-rows x 256 cols from its TMEM
    const int row = row0 + wid * 32 + lane;
    #pragma unroll 1
    for (int ch = 0; ch < 8; ch++) {
        uint32_t d[32];
        TCGEN05_LD_32X32B_X32(d, tmem + ch * 32);
        TCGEN05_WAIT_LD();
        const int colb = col0 + ch * 32;
        if (mode == 0) {
            float* dst = Cf + (long long)z * sC + (long long)row * ldc + colb;
            #pragma unroll
            for (int j = 0; j < 32; j += 4) {
                float4 v;
                v.x = __uint_as_float(d[j + 0]);
                v.y = __uint_as_float(d[j + 1]);
                v.z = __uint_as_float(d[j + 2]);
                v.w = __uint_as_float(d[j + 3]);
                *(float4*)(dst + j) = v;
            }
        } else {
            long long rbase = (long long)z * sC + (long long)row * ldc;
            #pragma unroll
            for (int j = 0; j < 32; j += 2) {
                int col = colb + j;
                float v0 = __uint_as_float(d[j + 0]) + bias[col + 0];
                float v1 = __uint_as_float(d[j + 1]) + bias[col + 1];
                __nv_bfloat16 h0, l0, h1, l1;
                split1(v0, h0, l0); split1(v1, h1, l1);
                __nv_bfloat162 hh; hh.x = h0; hh.y = h1;
                __nv_bfloat162 ll; ll.x = l0; ll.y = l1;
                *(__nv_bfloat162*)(Cs + rbase + col)        = hh;
                *(__nv_bfloat162*)(Cs + rbase + Nseg + col) = ll;
            }
        }
    }
    __syncthreads();
    CLUSTER_SYNC();
    if (wid == 0) {
        TCGEN05_RELINQ_CG2();
        TCGEN05_DEALLOC_CG2(tmem, 256);
    }
    CLUSTER_SYNC();
}

// ---------------------------------------------------------------------------
// softmax (in place, fp32) + split to acat [hi TV | lo TV]
// ---------------------------------------------------------------------------
__device__ __forceinline__ float warpMax(float v) {
    #pragma unroll
    for (int o = 16; o > 0; o >>= 1) v = fmaxf(v, __shfl_xor_sync(0xffffffffu, v, o));
    return v;
}
__device__ __forceinline__ float warpSum(float v) {
    #pragma unroll
    for (int o = 16; o > 0; o >>= 1) v += __shfl_xor_sync(0xffffffffu, v, o);
    return v;
}

__global__ __launch_bounds__(256)
void softmax_split(float* __restrict__ data, __nv_bfloat16* __restrict__ cat)
{
    const long long row = blockIdx.x;
    float* r = data + row * TV;
    const int tid = threadIdx.x, lane = tid & 31, warp = tid >> 5;
    __shared__ float sred[8];

    float v[8];
    *(float4*)(v)     = *(const float4*)(r + tid * 8);
    *(float4*)(v + 4) = *(const float4*)(r + tid * 8 + 4);

    float m = v[0];
    #pragma unroll
    for (int i = 1; i < 8; i++) m = fmaxf(m, v[i]);
    m = warpMax(m);
    if (lane == 0) sred[warp] = m;
    __syncthreads();
    m = (lane < 8) ? sred[lane] : -INFINITY;
    m = warpMax(m);
    m = __shfl_sync(0xffffffffu, m, 0);
    __syncthreads();

    float s = 0.f;
    #pragma unroll
    for (int i = 0; i < 8; i++) { v[i] = expf(v[i] - m); s += v[i]; }
    s = warpSum(s);
    if (lane == 0) sred[warp] = s;
    __syncthreads();
    s = (lane < 8) ? sred[lane] : 0.f;
    s = warpSum(s);
    s = __shfl_sync(0xffffffffu, s, 0);
    const float inv = 1.0f / s;

    #pragma unroll
    for (int i = 0; i < 8; i++) v[i] *= inv;
    *(float4*)(r + tid * 8)     = *(float4*)(v);
    *(float4*)(r + tid * 8 + 4) = *(float4*)(v + 4);

    __nv_bfloat16 h[8], l[8];
    #pragma unroll
    for (int i = 0; i < 8; i++) split1(v[i], h[i], l[i]);
    uint4 hh, ll;
    uint2 a0 = pack4(h[0], h[1], h[2], h[3]), a1 = pack4(h[4], h[5], h[6], h[7]);
    uint2 b0 = pack4(l[0], l[1], l[2], l[3]), b1 = pack4(l[4], l[5], l[6], l[7]);
    hh.x = a0.x; hh.y = a0.y; hh.z = a1.x; hh.w = a1.y;
    ll.x = b0.x; ll.y = b0.y; ll.z = b1.x; ll.w = b1.y;
    __nv_bfloat16* cbase = cat + row * (long long)(2 * TV) + tid * 8;
    *(uint4*)(cbase)      = hh;
    *(uint4*)(cbase + TV) = ll;
}

// ---------------------------------------------------------------------------
// launch — compile-time cluster, plain <<<>>> (graph-capture friendly)
// ---------------------------------------------------------------------------
extern "C" void kernel_launch(void* const* d_in, const int* in_sizes, int n_in,
                              void* d_out, int out_size)
{
    const float* query  = (const float*)d_in[0];  // [B, TQ, UNITS]
    const float* values = (const float*)d_in[1];  // [B, TV, DIM]
    const float* Wk     = (const float*)d_in[2];  // [DIM, UNITS]
    const float* Wb     = (const float*)d_in[3];  // [UNITS]

    float* ctx   = (float*)d_out;                             // [B, TQ, DIM]
    float* align = (float*)d_out + (size_t)BATCH * TQ * DIM;  // [B, TQ, TV]

    __nv_bfloat16 *qcat, *vcat, *wtcat, *kcat, *vtcat, *acat;
    cudaGetSymbolAddress((void**)&qcat,  g_qcat);
    cudaGetSymbolAddress((void**)&vcat,  g_vcat);
    cudaGetSymbolAddress((void**)&wtcat, g_wtcat);
    cudaGetSymbolAddress((void**)&kcat,  g_kcat);
    cudaGetSymbolAddress((void**)&vtcat, g_vtcat);
    cudaGetSymbolAddress((void**)&acat,  g_acat);

    cudaFuncSetAttribute(tcgemm2, cudaFuncAttributeMaxDynamicSharedMemorySize, GSMEM_BYTES);

    // prep
    {
        long long n = (long long)BATCH * TQ * UNITS;
        split_rows<<<(unsigned)(n / 4 / 256), 256>>>(query, qcat, n, UNITS);
    }
    {
        long long n = (long long)BATCH * TV * DIM;
        split_rows<<<(unsigned)(n / 4 / 256), 256>>>(values, vcat, n, DIM);
    }
    {
        dim3 g(DIM / 32, UNITS / 32, 1);
        transpose_split<<<g, dim3(32, 8)>>>(Wk, wtcat, DIM, UNITS, 0, 0);
    }
    {
        dim3 g(TV / 32, DIM / 32, BATCH);
        transpose_split<<<g, dim3(32, 8)>>>(values, vtcat, TV, DIM,
                                            (long long)TV * DIM, (long long)DIM * 2 * TV);
    }

    // GEMM1: keys = split(values @ W + b)  M=32768 N=1024 Kseg=1024
    {
        dim3 g(2 * UNITS / 256, (BATCH * TV) / 256, 1);  // (8, 128)
        tcgemm2<<<g, 128, GSMEM_BYTES>>>(vcat, wtcat, nullptr, kcat, Wb,
                                         1024, 4, 2 * DIM, 2 * DIM, 2 * UNITS,
                                         0, 0, 0, UNITS, 1);
    }

    // GEMM2: score = Q @ keys^T per batch  M=2048 N=2048 Kseg=1024 -> align fp32
    {
        dim3 g(2 * TV / 256, TQ / 256, BATCH);  // (16, 8, 16)
        tcgemm2<<<g, 128, GSMEM_BYTES>>>(qcat, kcat, align, nullptr, nullptr,
                                         1024, 4, 2 * UNITS, 2 * UNITS, TV,
                                         (long long)TQ * 2 * UNITS,
                                         (long long)TV * 2 * UNITS,
                                         (long long)TQ * TV, 0, 0);
    }

    // softmax + split
    softmax_split<<<BATCH * TQ, 256>>>(align, acat);

    // GEMM3: context = align @ values per batch  M=2048 N=1024 Kseg=2048
    {
        dim3 g(2 * DIM / 256, TQ / 256, BATCH);  // (8, 8, 16)
        tcgemm2<<<g, 128, GSMEM_BYTES>>>(acat, vtcat, ctx, nullptr, nullptr,
                                         2048, 5, 2 * TV, 2 * TV, DIM,
                                         (long long)TQ * 2 * TV,
                                         (long long)DIM * 2 * TV,
                                         (long long)TQ * DIM, 0, 0);
    }
}

// round 10
// speedup vs baseline: 2.6003x; 2.6003x over previous
#include <cuda_runtime.h>
#include <cuda_bf16.h>
#include <math.h>
#include <stdint.h>

// ---------------------------------------------------------------------------
// Problem dims
// ---------------------------------------------------------------------------
#define BATCH 16
#define TQ 2048
#define TV 2048
#define DIM 1024
#define UNITS 1024

// ---------------------------------------------------------------------------
// tcgen05 guard for the plain compute_103 PTX pass
// ---------------------------------------------------------------------------
#if defined(__CUDA_ARCH_FEAT_SM103_ALL) || defined(__CUDA_ARCH_FEAT_SM100_ALL) || defined(__CUDA_ARCH_FEAT_SM101_ALL)
#define TCOK 1
#else
#define TCOK 0
#endif

// ---------------------------------------------------------------------------
// Scratch: [hi | lo] storage, row stride 2*K
// ---------------------------------------------------------------------------
__device__ __nv_bfloat16 g_qcat[(size_t)BATCH * TQ * 2 * UNITS];  // query  [hi|lo]
__device__ __nv_bfloat16 g_vcat[(size_t)BATCH * TV * 2 * DIM];    // values [hi|lo]
__device__ __nv_bfloat16 g_wtcat[(size_t)UNITS * 2 * DIM];        // W^T    [hi|lo]
__device__ __nv_bfloat16 g_kcat[(size_t)BATCH * TV * 2 * UNITS];  // keys   [hi|lo]
__device__ __nv_bfloat16 g_vtcat[(size_t)BATCH * DIM * 2 * TV];   // V^T    [hi|lo]
__device__ __nv_bfloat16 g_acat[(size_t)BATCH * TQ * 2 * TV];     // align  [hi|lo]

// ---------------------------------------------------------------------------
// PTX helpers
// ---------------------------------------------------------------------------
__device__ __forceinline__ uint32_t smem_u32(const void* p) {
    uint32_t a;
    asm("{ .reg .u64 t; cvta.to.shared.u64 t, %1; cvt.u32.u64 %0, t; }" : "=r"(a) : "l"(p));
    return a;
}
__device__ __forceinline__ uint32_t elect_one_pred() {
    uint32_t pred;
    asm volatile("{\n\t.reg .pred p;\n\telect.sync _|p, 0xFFFFFFFF;\n\tselp.b32 %0, 1, 0, p;\n\t}" : "=r"(pred));
    return pred;
}
#define MBARRIER_INIT(addr, cnt) \
    asm volatile("mbarrier.init.shared.b64 [%0], %1;" :: "r"(addr), "r"((uint32_t)(cnt)) : "memory")
#define MBARRIER_WAIT_PARITY(addr, parity) do { \
    uint32_t _m = (addr); uint32_t _p = (uint32_t)(parity); uint32_t _d; \
    asm volatile("{\n\t.reg .pred p;\n\tmbarrier.try_wait.parity.acquire.cta.shared::cta.b64 p, [%1], %2;\n\tselp.b32 %0, 1, 0, p;\n\t}" \
        : "=r"(_d) : "r"(_m), "r"(_p) : "memory"); \
    if (!_d) { \
        asm volatile("{\n\t.reg .pred P1;\n\tWL_%=:\n\tmbarrier.try_wait.parity.acquire.cta.shared::cta.b64 P1, [%0], %1, 0x989680;\n\t@P1 bra.uni WD_%=;\n\tbra.uni WL_%=;\n\tWD_%=:\n\t}" \
            :: "r"(_m), "r"(_p) : "memory"); \
    } } while (0)

#if TCOK
#define TCGEN05_ALLOC(sp, n) \
    asm volatile("tcgen05.alloc.cta_group::1.sync.aligned.shared::cta.b32 [%0], %1;" :: "r"(sp), "r"((uint32_t)(n)) : "memory")
#define TCGEN05_DEALLOC(t, n) \
    asm volatile("tcgen05.dealloc.cta_group::1.sync.aligned.b32 %0, %1;" :: "r"(t), "r"((uint32_t)(n)))
#define TCGEN05_RELINQ() \
    asm volatile("tcgen05.relinquish_alloc_permit.cta_group::1.sync.aligned;")
#define TCGEN05_COMMIT(mb) \
    asm volatile("tcgen05.commit.cta_group::1.mbarrier::arrive::one.shared::cluster.b64 [%0];" :: "r"(mb) : "memory")
#define TCGEN05_FENCE_AFTER() asm volatile("tcgen05.fence::after_thread_sync;" ::: "memory")
#define TCGEN05_WAIT_LD()     asm volatile("tcgen05.wait::ld.sync.aligned;" ::: "memory")
#define TCGEN05_LD_32X32B_X32(r, ta) \
    asm volatile("tcgen05.ld.sync.aligned.32x32b.x32.b32 " \
        "{%0, %1, %2, %3, %4, %5, %6, %7, %8, %9, %10, %11, %12, %13, %14, %15, " \
        " %16, %17, %18, %19, %20, %21, %22, %23, %24, %25, %26, %27, %28, %29, %30, %31}, [%32];" \
        : "=r"((r)[0]), "=r"((r)[1]), "=r"((r)[2]), "=r"((r)[3]), "=r"((r)[4]), "=r"((r)[5]), "=r"((r)[6]), "=r"((r)[7]), \
          "=r"((r)[8]), "=r"((r)[9]), "=r"((r)[10]), "=r"((r)[11]), "=r"((r)[12]), "=r"((r)[13]), "=r"((r)[14]), "=r"((r)[15]), \
          "=r"((r)[16]), "=r"((r)[17]), "=r"((r)[18]), "=r"((r)[19]), "=r"((r)[20]), "=r"((r)[21]), "=r"((r)[22]), "=r"((r)[23]), \
          "=r"((r)[24]), "=r"((r)[25]), "=r"((r)[26]), "=r"((r)[27]), "=r"((r)[28]), "=r"((r)[29]), "=r"((r)[30]), "=r"((r)[31]) \
        : "r"(ta))
#else
#define TCGEN05_ALLOC(sp, n)  ((void)0)
#define TCGEN05_DEALLOC(t, n) ((void)0)
#define TCGEN05_RELINQ()      ((void)0)
#define TCGEN05_COMMIT(mb)    ((void)0)
#define TCGEN05_FENCE_AFTER() ((void)0)
#define TCGEN05_WAIT_LD()     ((void)0)
#define TCGEN05_LD_32X32B_X32(r, ta) do { \
    _Pragma("unroll") for (int _i = 0; _i < 32; _i++) (r)[_i] = 0u; (void)(ta); } while (0)
#endif

#define CP_ASYNC16(dst, src) \
    asm volatile("cp.async.cg.shared.global [%0], [%1], 16;" :: "r"(dst), "l"(src) : "memory")
#define CP_COMMIT() asm volatile("cp.async.commit_group;" ::: "memory")
#define CP_WAIT(n)  asm volatile("cp.async.wait_group %0;" :: "n"(n) : "memory")
#define FENCE_ASYNC_SHARED() asm volatile("fence.proxy.async.shared::cta;" ::: "memory")

#define SMEM_SWIZZLE_128B(off) ((off) ^ (((off) >> 3) & 0x70))

static __device__ __forceinline__ uint64_t make_desc(uint32_t addr) {
    const uint64_t base =
        (uint64_t(2) << 61) | (uint64_t(1) << 46) | (uint64_t(64) << 32) | (uint64_t(1) << 16);
    return base | ((uint64_t)(addr >> 4) & 0x3FFF);
}

// idesc kind::f16 bf16xbf16->f32, M=128, N=256
#define GEMM_IDESC 0x8400490u

__device__ __forceinline__ void mma_f16_ss(uint32_t d, uint64_t ad, uint64_t bd, uint32_t en) {
#if TCOK
    asm volatile(
        "{\n\t.reg .pred p;\n\tsetp.ne.u32 p, %5, 0;\n\t"
        "tcgen05.mma.cta_group::1.kind::f16 [%0], %1, %2, %3, {%4, %4, %4, %4}, p;\n\t}"
        :: "r"(d), "l"(ad), "l"(bd), "r"(GEMM_IDESC), "r"(0u), "r"(en) : "memory");
#else
    (void)d; (void)ad; (void)bd; (void)en;
#endif
}

// ---------------------------------------------------------------------------
// split helpers
// ---------------------------------------------------------------------------
__device__ __forceinline__ void split1(float v, __nv_bfloat16& h, __nv_bfloat16& l) {
    h = __float2bfloat16(v);
    l = __float2bfloat16(v - __bfloat162float(h));
}
__device__ __forceinline__ uint2 pack4(__nv_bfloat16 a, __nv_bfloat16 b, __nv_bfloat16 c, __nv_bfloat16 d) {
    __nv_bfloat162 p0; p0.x = a; p0.y = b;
    __nv_bfloat162 p1; p1.x = c; p1.y = d;
    uint2 r;
    r.x = *reinterpret_cast<uint32_t*>(&p0);
    r.y = *reinterpret_cast<uint32_t*>(&p1);
    return r;
}

// fp32 [.., K] -> bf16 [hi K | lo K], row stride 2K
__global__ __launch_bounds__(256)
void split_rows(const float* __restrict__ src, __nv_bfloat16* __restrict__ dst,
                long long n, int K)
{
    long long e = ((long long)blockIdx.x * 256 + threadIdx.x) * 4;
    if (e >= n) return;
    float4 v = *(const float4*)(src + e);
    long long m = e / K;
    int k = (int)(e - m * K);
    __nv_bfloat16 h0, h1, h2, h3, l0, l1, l2, l3;
    split1(v.x, h0, l0); split1(v.y, h1, l1); split1(v.z, h2, l2); split1(v.w, h3, l3);
    long long base = m * (long long)(2 * K) + k;
    *(uint2*)(dst + base)     = pack4(h0, h1, h2, h3);
    *(uint2*)(dst + base + K) = pack4(l0, l1, l2, l3);
}

// transpose + split: src [R, C] fp32 -> dst [C, 2R] bf16 ([hi R | lo R])
__global__ __launch_bounds__(256)
void transpose_split(const float* __restrict__ src, __nv_bfloat16* __restrict__ dst,
                     int R, int C, long long sSrc, long long sDst)
{
    __shared__ float t[32][33];
    src += (long long)blockIdx.z * sSrc;
    dst += (long long)blockIdx.z * sDst;
    int r0 = blockIdx.x * 32;
    int c0 = blockIdx.y * 32;
    int tx = threadIdx.x, ty = threadIdx.y;  // block (32, 8)
    #pragma unroll
    for (int i = 0; i < 4; i++)
        t[ty + i * 8][tx] = src[(long long)(r0 + ty + i * 8) * C + (c0 + tx)];
    __syncthreads();
    #pragma unroll
    for (int i = 0; i < 4; i++) {
        int dr = c0 + ty + i * 8;
        int dc = r0 + tx;
        float v = t[tx][ty + i * 8];
        __nv_bfloat16 h, l; split1(v, h, l);
        __nv_bfloat16* p = dst + (long long)dr * (2 * R) + dc;
        p[0] = h;
        p[R] = l;
    }
}

// ---------------------------------------------------------------------------
// fused values prep: ONE read of values produces BOTH
//   vcat  [TV rows, 2*DIM]  ([hi DIM | lo DIM])
//   vtcat [DIM rows, 2*TV]  ([hi TV  | lo TV ])
// grid (DIM/32, TV/32, BATCH), block 256. 32x32 fp32 tile via smem.
// ---------------------------------------------------------------------------
__global__ __launch_bounds__(256)
void prep_values(const float* __restrict__ src,
                 __nv_bfloat16* __restrict__ vcat,
                 __nv_bfloat16* __restrict__ vtcat)
{
    __shared__ float t[32][33];
    const int z = blockIdx.z;
    const float* s = src + (long long)z * TV * DIM;
    __nv_bfloat16* vc = vcat  + (long long)z * TV * 2 * DIM;
    __nv_bfloat16* vt = vtcat + (long long)z * DIM * 2 * TV;
    const int c0 = blockIdx.x * 32;   // DIM offset
    const int r0 = blockIdx.y * 32;   // TV offset
    const int tid = threadIdx.x;

    // phase 1: float4 read + vcat write (wide) + smem deposit
    {
        const int row = tid >> 3;        // 0..31
        const int cg  = (tid & 7) * 4;   // 0..28
        float4 v = *(const float4*)(s + (long long)(r0 + row) * DIM + c0 + cg);
        __nv_bfloat16 h0, h1, h2, h3, l0, l1, l2, l3;
        split1(v.x, h0, l0); split1(v.y, h1, l1); split1(v.z, h2, l2); split1(v.w, h3, l3);
        long long vbase = (long long)(r0 + row) * (2 * DIM) + c0 + cg;
        *(uint2*)(vc + vbase)       = pack4(h0, h1, h2, h3);
        *(uint2*)(vc + vbase + DIM) = pack4(l0, l1, l2, l3);
        t[row][cg + 0] = v.x;
        t[row][cg + 1] = v.y;
        t[row][cg + 2] = v.z;
        t[row][cg + 3] = v.w;
    }
    __syncthreads();

    // phase 2: transposed wide write to vtcat
    {
        const int drl = tid >> 3;        // src col 0..31 -> vt row c0+drl
        const int rg  = (tid & 7) * 4;   // src rows rg..rg+3 -> vt cols r0+rg..
        float a0 = t[rg + 0][drl];
        float a1 = t[rg + 1][drl];
        float a2 = t[rg + 2][drl];
        float a3 = t[rg + 3][drl];
        __nv_bfloat16 h0, h1, h2, h3, l0, l1, l2, l3;
        split1(a0, h0, l0); split1(a1, h1, l1); split1(a2, h2, l2); split1(a3, h3, l3);
        long long tbase = (long long)(c0 + drl) * (2 * TV) + r0 + rg;
        *(uint2*)(vt + tbase)      = pack4(h0, h1, h2, h3);
        *(uint2*)(vt + tbase + TV) = pack4(l0, l1, l2, l3);
    }
}

// ---------------------------------------------------------------------------
// tcgen05 GEMM over logical segments (A: {hi,lo,hi}, B: {hi,hi,lo})
//   128x256 tile per CTA (A 128 rows, B 256 rows), KBLK=64,
//   2-stage cp.async double buffer -> 97KB smem, 2 CTAs/SM, TMEM 256 cols.
// mode 0: fp32 out Cf. mode 1: bias + split out Cs ([hi|lo], lo at +Nseg).
// ---------------------------------------------------------------------------
#define KBLK 64
#define ATILE 16384   // 128 rows x 128B
#define BTILE 32768   // 256 rows x 128B
#define GSMEM_BYTES (1024 + 2 * (ATILE + BTILE))

__global__ __launch_bounds__(128)
void tcgemm(const __nv_bfloat16* __restrict__ A, const __nv_bfloat16* __restrict__ B,
            float* __restrict__ Cf, __nv_bfloat16* __restrict__ Cs,
            const float* __restrict__ bias,
            int Kseg, int blkShift, int lda, int ldb, int ldc,
            long long sA, long long sB, long long sC,
            int Nseg, int mode)
{
    extern __shared__ char dsm[];
    uint32_t sbase = (smem_u32(dsm) + 1023) & ~1023u;
    const uint32_t tptr  = sbase;
    const uint32_t mbar0 = sbase + 8;
    const uint32_t aoff0 = sbase + 1024;
    const uint32_t aoff1 = aoff0 + ATILE;
    const uint32_t boff0 = aoff1 + ATILE;
    const uint32_t boff1 = boff0 + BTILE;
    const uint32_t Aoff[2] = {aoff0, aoff1};
    const uint32_t Boff[2] = {boff0, boff1};

    const int tid = threadIdx.x;
    const int wid = tid >> 5;
    const int lane = tid & 31;
    const int z = blockIdx.z;

    if (wid == 0) {
        TCGEN05_ALLOC(tptr, 256);
        TCGEN05_RELINQ();
    }
    if (tid == 0) {
        MBARRIER_INIT(mbar0, 1);
        MBARRIER_INIT(mbar0 + 8, 1);
    }
    __syncthreads();
    uint32_t tmem;
    asm volatile("ld.shared.b32 %0, [%1];" : "=r"(tmem) : "r"(tptr));

    const __nv_bfloat16* Ab = A + (long long)z * sA;
    const __nv_bfloat16* Bb = B + (long long)z * sB;
    const int row0 = blockIdx.y * 128;
    const int col0 = blockIdx.x * 256;

    // segment tables (column offsets into [hi|lo] storage)
    const int segA[3] = {0, Kseg, 0};
    const int segB[3] = {0, 0, Kseg};
    const int perSegM1 = (1 << blkShift) - 1;
    const int nkb = 3 << blkShift;

    auto colOf = [&](int kb, const int* seg) {
        return seg[kb >> blkShift] + (kb & perSegM1) * KBLK;
    };

    // rows x 64 bf16 (128B/row), SW128 swizzle; nIter = rows*8/128
    auto load_tile = [&](uint32_t smemTile, const __nv_bfloat16* g, int ld, int r0g, int cb, int nIter) {
        for (int s = 0; s < nIter; s++) {
            int id = tid + s * 128;
            int r = id >> 3;
            int c = id & 7;
            const char* src = (const char*)(g + (long long)(r0g + r) * ld + cb) + c * 16;
            uint32_t dst = smemTile + SMEM_SWIZZLE_128B(r * 128 + c * 16);
            CP_ASYNC16(dst, src);
        }
    };

    int ph[2] = {0, 0};

    load_tile(Aoff[0], Ab, lda, row0, colOf(0, segA), 8);
    load_tile(Boff[0], Bb, ldb, col0, colOf(0, segB), 16);
    CP_COMMIT();

    for (int kb = 0; kb < nkb; kb++) {
        const int buf = kb & 1, nb = buf ^ 1;
        if (kb + 1 < nkb) {
            if (kb >= 1) {  // buffer nb last used by MMA block kb-1
                MBARRIER_WAIT_PARITY(mbar0 + 8 * nb, ph[nb] & 1);
                ph[nb]++;
            }
            load_tile(Aoff[nb], Ab, lda, row0, colOf(kb + 1, segA), 8);
            load_tile(Boff[nb], Bb, ldb, col0, colOf(kb + 1, segB), 16);
            CP_COMMIT();
            CP_WAIT(1);
        } else {
            CP_WAIT(0);
        }
        FENCE_ASYNC_SHARED();
        __syncthreads();
        if (wid == 0) {
            if (elect_one_pred()) {
                uint64_t ad = make_desc(Aoff[buf]);
                uint64_t bd = make_desc(Boff[buf]);
                #pragma unroll
                for (int s = 0; s < 4; s++)
                    mma_f16_ss(tmem, ad + s * 2, bd + s * 2, (kb > 0 || s > 0) ? 1u : 0u);
                TCGEN05_COMMIT(mbar0 + 8 * buf);
            }
        }
    }

    const int lastbuf = (nkb - 1) & 1;
    MBARRIER_WAIT_PARITY(mbar0 + 8 * lastbuf, ph[lastbuf] & 1);
    TCGEN05_FENCE_AFTER();

    const int row = row0 + wid * 32 + lane;
    #pragma unroll 1
    for (int ch = 0; ch < 8; ch++) {
        uint32_t d[32];
        TCGEN05_LD_32X32B_X32(d, tmem + ch * 32);
        TCGEN05_WAIT_LD();
        const int colb = col0 + ch * 32;
        if (mode == 0) {
            float* dst = Cf + (long long)z * sC + (long long)row * ldc + colb;
            #pragma unroll
            for (int j = 0; j < 32; j += 4) {
                float4 v;
                v.x = __uint_as_float(d[j + 0]);
                v.y = __uint_as_float(d[j + 1]);
                v.z = __uint_as_float(d[j + 2]);
                v.w = __uint_as_float(d[j + 3]);
                *(float4*)(dst + j) = v;
            }
        } else {
            long long rbase = (long long)z * sC + (long long)row * ldc;
            #pragma unroll
            for (int j = 0; j < 32; j += 2) {
                int col = colb + j;
                float v0 = __uint_as_float(d[j + 0]) + bias[col + 0];
                float v1 = __uint_as_float(d[j + 1]) + bias[col + 1];
                __nv_bfloat16 h0, l0, h1, l1;
                split1(v0, h0, l0); split1(v1, h1, l1);
                __nv_bfloat162 hh; hh.x = h0; hh.y = h1;
                __nv_bfloat162 ll; ll.x = l0; ll.y = l1;
                *(__nv_bfloat162*)(Cs + rbase + col)        = hh;
                *(__nv_bfloat162*)(Cs + rbase + Nseg + col) = ll;
            }
        }
    }
    __syncthreads();
    if (wid == 0) TCGEN05_DEALLOC(tmem, 256);
}

// ---------------------------------------------------------------------------
// softmax (in place, fp32) + split to acat [hi TV | lo TV]
// ---------------------------------------------------------------------------
__device__ __forceinline__ float warpMax(float v) {
    #pragma unroll
    for (int o = 16; o > 0; o >>= 1) v = fmaxf(v, __shfl_xor_sync(0xffffffffu, v, o));
    return v;
}
__device__ __forceinline__ float warpSum(float v) {
    #pragma unroll
    for (int o = 16; o > 0; o >>= 1) v += __shfl_xor_sync(0xffffffffu, v, o);
    return v;
}

__global__ __launch_bounds__(256)
void softmax_split(float* __restrict__ data, __nv_bfloat16* __restrict__ cat)
{
    const long long row = blockIdx.x;
    float* r = data + row * TV;
    const int tid = threadIdx.x, lane = tid & 31, warp = tid >> 5;
    __shared__ float sred[8];

    float v[8];
    *(float4*)(v)     = *(const float4*)(r + tid * 8);
    *(float4*)(v + 4) = *(const float4*)(r + tid * 8 + 4);

    float m = v[0];
    #pragma unroll
    for (int i = 1; i < 8; i++) m = fmaxf(m, v[i]);
    m = warpMax(m);
    if (lane == 0) sred[warp] = m;
    __syncthreads();
    m = (lane < 8) ? sred[lane] : -INFINITY;
    m = warpMax(m);
    m = __shfl_sync(0xffffffffu, m, 0);
    __syncthreads();

    float s = 0.f;
    #pragma unroll
    for (int i = 0; i < 8; i++) { v[i] = expf(v[i] - m); s += v[i]; }
    s = warpSum(s);
    if (lane == 0) sred[warp] = s;
    __syncthreads();
    s = (lane < 8) ? sred[lane] : 0.f;
    s = warpSum(s);
    s = __shfl_sync(0xffffffffu, s, 0);
    const float inv = 1.0f / s;

    #pragma unroll
    for (int i = 0; i < 8; i++) v[i] *= inv;
    *(float4*)(r + tid * 8)     = *(float4*)(v);
    *(float4*)(r + tid * 8 + 4) = *(float4*)(v + 4);

    __nv_bfloat16 h[8], l[8];
    #pragma unroll
    for (int i = 0; i < 8; i++) split1(v[i], h[i], l[i]);
    uint4 hh, ll;
    uint2 a0 = pack4(h[0], h[1], h[2], h[3]), a1 = pack4(h[4], h[5], h[6], h[7]);
    uint2 b0 = pack4(l[0], l[1], l[2], l[3]), b1 = pack4(l[4], l[5], l[6], l[7]);
    hh.x = a0.x; hh.y = a0.y; hh.z = a1.x; hh.w = a1.y;
    ll.x = b0.x; ll.y = b0.y; ll.z = b1.x; ll.w = b1.y;
    __nv_bfloat16* cbase = cat + row * (long long)(2 * TV) + tid * 8;
    *(uint4*)(cbase)      = hh;
    *(uint4*)(cbase + TV) = ll;
}

// ---------------------------------------------------------------------------
// launch
// ---------------------------------------------------------------------------
extern "C" void kernel_launch(void* const* d_in, const int* in_sizes, int n_in,
                              void* d_out, int out_size)
{
    const float* query  = (const float*)d_in[0];  // [B, TQ, UNITS]
    const float* values = (const float*)d_in[1];  // [B, TV, DIM]
    const float* Wk     = (const float*)d_in[2];  // [DIM, UNITS]
    const float* Wb     = (const float*)d_in[3];  // [UNITS]

    float* ctx   = (float*)d_out;                             // [B, TQ, DIM]
    float* align = (float*)d_out + (size_t)BATCH * TQ * DIM;  // [B, TQ, TV]

    __nv_bfloat16 *qcat, *vcat, *wtcat, *kcat, *vtcat, *acat;
    cudaGetSymbolAddress((void**)&qcat,  g_qcat);
    cudaGetSymbolAddress((void**)&vcat,  g_vcat);
    cudaGetSymbolAddress((void**)&wtcat, g_wtcat);
    cudaGetSymbolAddress((void**)&kcat,  g_kcat);
    cudaGetSymbolAddress((void**)&vtcat, g_vtcat);
    cudaGetSymbolAddress((void**)&acat,  g_acat);

    cudaFuncSetAttribute(tcgemm, cudaFuncAttributeMaxDynamicSharedMemorySize, GSMEM_BYTES);

    // prep
    {
        long long n = (long long)BATCH * TQ * UNITS;
        split_rows<<<(unsigned)(n / 4 / 256), 256>>>(query, qcat, n, UNITS);
    }
    {
        dim3 g(DIM / 32, TV / 32, BATCH);
        prep_values<<<g, 256>>>(values, vcat, vtcat);
    }
    {
        dim3 g(DIM / 32, UNITS / 32, 1);
        transpose_split<<<g, dim3(32, 8)>>>(Wk, wtcat, DIM, UNITS, 0, 0);
    }

    // GEMM1: keys = split(values @ W + b)  M=32768 N=1024 Kseg=1024
    {
        dim3 g(UNITS / 256, (BATCH * TV) / 128, 1);
        tcgemm<<<g, 128, GSMEM_BYTES>>>(vcat, wtcat, nullptr, kcat, Wb,
                                        1024, 4, 2 * DIM, 2 * DIM, 2 * UNITS,
                                        0, 0, 0, UNITS, 1);
    }

    // GEMM2: score = Q @ keys^T per batch  M=2048 N=2048 Kseg=1024 -> align fp32
    {
        dim3 g(TV / 256, TQ / 128, BATCH);
        tcgemm<<<g, 128, GSMEM_BYTES>>>(qcat, kcat, align, nullptr, nullptr,
                                        1024, 4, 2 * UNITS, 2 * UNITS, TV,
                                        (long long)TQ * 2 * UNITS,
                                        (long long)TV * 2 * UNITS,
                                        (long long)TQ * TV, 0, 0);
    }

    // softmax + split
    softmax_split<<<BATCH * TQ, 256>>>(align, acat);

    // GEMM3: context = align @ values per batch  M=2048 N=1024 Kseg=2048
    {
        dim3 g(DIM / 256, TQ / 128, BATCH);
        tcgemm<<<g, 128, GSMEM_BYTES>>>(acat, vtcat, ctx, nullptr, nullptr,
                                        2048, 5, 2 * TV, 2 * TV, DIM,
                                        (long long)TQ * 2 * TV,
                                        (long long)DIM * 2 * TV,
                                        (long long)TQ * DIM, 0, 0);
    }
}